// round 5
// baseline (speedup 1.0000x reference)
#include <cuda_runtime.h>
#include <cstdint>

typedef uint32_t u32;

#define Dq 128
#define MAXN 50000

// ---------------- device scratch ----------------
__device__ float g_agg[(size_t)MAXN * Dq];
__device__ float g_aggc[(size_t)MAXN * 4];
__device__ int   g_is64;
__device__ float g_h32[(size_t)MAXN * Dq];   // tf32-rounded h
__device__ float gWe1r[256 * 128];           // tf32-rounded weights (k-major)
__device__ float gWe2r[128 * 128];
__device__ float gWc1r[128 * 128];
__device__ float gWn1r[256 * 128];
__device__ float gWn2r[128 * 128];

// ---------------- helpers ----------------
__device__ __forceinline__ float silu_f(float x) {
    return x * (1.0f / (1.0f + __expf(-x)));
}
__device__ __forceinline__ u32 tf32r(float f) {
    u32 u; asm("cvt.rna.tf32.f32 %0, %1;" : "=r"(u) : "f"(f)); return u;
}
__device__ __forceinline__ u32 smem_u32(const void* p) {
    u32 a;
    asm("{ .reg .u64 t; cvta.to.shared.u64 t, %1; cvt.u32.u64 %0, t; }" : "=r"(a) : "l"(p));
    return a;
}
__device__ __forceinline__ void cpa16(u32 d, const void* s) {
    asm volatile("cp.async.ca.shared.global [%0], [%1], 16;" :: "r"(d), "l"(s) : "memory");
}
#define CP_COMMIT() asm volatile("cp.async.commit_group;" ::: "memory")
template<int N> __device__ __forceinline__ void cp_wait() {
    asm volatile("cp.async.wait_group %0;" :: "n"(N) : "memory");
}
__device__ __forceinline__ void mma8(float (&d)[4], const u32 (&a)[4], const u32 (&b)[2]) {
    asm volatile("mma.sync.aligned.m16n8k8.row.col.f32.tf32.tf32.f32 "
                 "{%0,%1,%2,%3}, {%4,%5,%6,%7}, {%8,%9}, {%0,%1,%2,%3};"
                 : "+f"(d[0]), "+f"(d[1]), "+f"(d[2]), "+f"(d[3])
                 : "r"(a[0]), "r"(a[1]), "r"(a[2]), "r"(a[3]), "r"(b[0]), "r"(b[1]));
}
__device__ __forceinline__ void red4(float* p, float a, float b, float c, float d) {
    asm volatile("red.global.add.v4.f32 [%0], {%1,%2,%3,%4};"
                 :: "l"(p), "f"(a), "f"(b), "f"(c), "f"(d) : "memory");
}

// ---------------- smem layout (float offsets) ----------------
// Region1 (17408 floats): A-staging (2 x 128 x 40 = 10240) during GEMM1,
//                         then act[128][136] from epi1 onward (aliased).
// Bs (8704 floats): 2 x 32 x 136 weight chunks.
#define SAa 40                // A-chunk row stride (32+8)
#define SB 136                // B-chunk / act row stride (128+8)
#define ABUF 5120             // floats per A buffer (128*40)
#define BBUF 4352             // floats per B buffer (32*136)
#define F_R1   0
#define F_BS   17408
#define F_MISC 26112
#define SMEM_FLOATS (F_MISC + 2048)
#define SMEM_BYTES (SMEM_FLOATS * 4)   // 112640

// ---------------- core warp GEMM: one K=32 chunk (4 k8-steps) ----------------
template<bool CVTA>
__device__ __forceinline__ void warp_gemm_chunk(
    const float* __restrict__ As_, int sa,
    const float* __restrict__ Bs_,
    int mb, int nb, int g, int tg,
    float (*acc)[8][4])
{
    #pragma unroll
    for (int ks = 0; ks < 4; ks++) {
        const int k = ks * 8;
        u32 a[2][4], b[8][2];
        #pragma unroll
        for (int mt = 0; mt < 2; mt++) {
            const float* ap = As_ + (mb + mt * 16 + g) * sa + k + tg;
            float f0 = ap[0], f1 = ap[8 * sa], f2 = ap[4], f3 = ap[8 * sa + 4];
            if (CVTA) {
                a[mt][0] = tf32r(f0); a[mt][1] = tf32r(f1);
                a[mt][2] = tf32r(f2); a[mt][3] = tf32r(f3);
            } else {
                a[mt][0] = __float_as_uint(f0); a[mt][1] = __float_as_uint(f1);
                a[mt][2] = __float_as_uint(f2); a[mt][3] = __float_as_uint(f3);
            }
        }
        #pragma unroll
        for (int nt = 0; nt < 8; nt++) {
            const float* bp = Bs_ + (k + tg) * SB + nb + nt * 8 + g;
            b[nt][0] = __float_as_uint(bp[0]);
            b[nt][1] = __float_as_uint(bp[4 * SB]);
        }
        #pragma unroll
        for (int mt = 0; mt < 2; mt++)
            #pragma unroll
            for (int nt = 0; nt < 8; nt++)
                mma8(acc[mt][nt], a[mt], b[nt]);
    }
}

// stage a [32][128] weight chunk into smem buffer
__device__ __forceinline__ void stageB(u32 bs_u32, int buf, const float* __restrict__ W,
                                       int k0, int tid) {
    #pragma unroll
    for (int i = tid; i < 1024; i += 256) {
        int k = i >> 5, q = i & 31;
        cpa16(bs_u32 + (u32)(buf * BBUF + k * SB + q * 4) * 4,
              W + (size_t)(k0 + k) * 128 + q * 4);
    }
}

// ---------------- small kernels ----------------
__global__ void detect_kernel(const int* __restrict__ ei32) {
    if (threadIdx.x == 0 && blockIdx.x == 0) {
        int acc = 0;
        #pragma unroll
        for (int k = 0; k < 128; k++) acc |= ei32[2 * k + 1];
        g_is64 = (acc == 0) ? 1 : 0;
    }
}
__global__ void zero_kernel(int Nn) {
    int stride = gridDim.x * blockDim.x;
    for (int i = blockIdx.x * blockDim.x + threadIdx.x; i < Nn * Dq; i += stride)
        g_agg[i] = 0.f;
    for (int i = blockIdx.x * blockDim.x + threadIdx.x; i < Nn * 4; i += stride)
        g_aggc[i] = 0.f;
}
__global__ void prep_cvt(const float* __restrict__ src, float* __restrict__ dst, int n) {
    int stride = gridDim.x * blockDim.x;
    for (int i = blockIdx.x * blockDim.x + threadIdx.x; i < n; i += stride)
        dst[i] = __uint_as_float(tf32r(src[i]));
}

// ================= edge kernel =================
__global__ __launch_bounds__(256, 2) void edge_kernel(
    const void* __restrict__ ei, const float* __restrict__ coord,
    const float* __restrict__ We1,
    const float* __restrict__ be1, const float* __restrict__ be2,
    const float* __restrict__ Watt, const float* __restrict__ batt,
    const float* __restrict__ bc1, const float* __restrict__ Wc2,
    float* __restrict__ ef_out, int E)
{
    extern __shared__ float sm[];
    float* R1  = sm + F_R1;       // A-chunks, then act
    float* act = sm + F_R1;
    float* Bs  = sm + F_BS;
    float* M   = sm + F_MISC;
    int*   s_row = (int*)(M);
    int*   s_col = (int*)(M + 128);
    float* s_cd  = M + 256;
    float* s_rad = M + 640;
    float* s_w256= M + 768;
    float* s_b1  = M + 896;
    float* s_b2  = M + 1024;
    float* s_bc1 = M + 1152;
    float* s_watt= M + 1280;
    float* s_wc2 = M + 1408;
    float* s_att = M + 1536;
    float* s_cwA = M + 1664;
    float* s_cwB = M + 1792;
    float* s_x   = M + 1920;

    const u32 r1_u32 = smem_u32(R1);
    const u32 bs_u32 = smem_u32(Bs);
    const int tid = threadIdx.x;
    const int wid = tid >> 5, lane = tid & 31;
    const int g = lane >> 2, tg = lane & 3;
    const int mb = (wid >> 1) * 32, nb = (wid & 1) * 64;
    const long long e0 = (long long)blockIdx.x * 128;
    const int half = wid & 1;

    // ---- meta + small vectors ----
    if (tid < 128) {
        long long e = e0 + tid;
        int r = 0, c = 0;
        if (e < E) {
            if (g_is64) {
                const long long* p = (const long long*)ei;
                r = (int)p[e]; c = (int)p[E + e];
            } else {
                const int* p = (const int*)ei;
                r = p[e]; c = p[E + e];
            }
        }
        s_row[tid] = r; s_col[tid] = c;
        float dx = coord[r * 3 + 0] - coord[c * 3 + 0];
        float dy = coord[r * 3 + 1] - coord[c * 3 + 1];
        float dz = coord[r * 3 + 2] - coord[c * 3 + 2];
        s_cd[tid * 3 + 0] = dx; s_cd[tid * 3 + 1] = dy; s_cd[tid * 3 + 2] = dz;
        s_rad[tid] = dx * dx + dy * dy + dz * dz;
        s_w256[tid] = We1[256 * 128 + tid];
        s_b1[tid] = be1[tid]; s_b2[tid] = be2[tid]; s_bc1[tid] = bc1[tid];
        s_watt[tid] = Watt[tid]; s_wc2[tid] = Wc2[tid];
        if (tid == 0) s_x[0] = batt[0];
    }
    __syncthreads();

    // A-chunk stage: chunk c (0..7): rows h32[row] (c<4) or h32[col], cols (c&3)*32
    auto stageA = [&](int c, int buf) {
        const float* base = g_h32 + (size_t)((c & 3) * 32);
        #pragma unroll
        for (int i = tid; i < 1024; i += 256) {
            int m = i >> 3, q = i & 7;
            int node = (c >= 4) ? s_col[m] : s_row[m];
            cpa16(r1_u32 + ((u32)buf * ABUF + (u32)(m * SAa + q * 4)) * 4,
                  base + (size_t)node * 128 + q * 4);
        }
    };

    float acc[2][8][4];
    #pragma unroll
    for (int mt = 0; mt < 2; mt++)
        #pragma unroll
        for (int nt = 0; nt < 8; nt++)
            #pragma unroll
            for (int t = 0; t < 4; t++) acc[mt][nt][t] = 0.f;

    // ======== GEMM1: K=256 over [h_row|h_col], 8 chunks of K=32 ========
    stageA(0, 0); stageB(bs_u32, 0, gWe1r, 0, tid); CP_COMMIT();
    #pragma unroll 1
    for (int c = 0; c < 8; c++) {
        if (c < 7) {
            stageA(c + 1, (c + 1) & 1);
            stageB(bs_u32, (c + 1) & 1, gWe1r, (c + 1) * 32, tid);
            CP_COMMIT(); cp_wait<1>();
        } else cp_wait<0>();
        __syncthreads();
        warp_gemm_chunk<false>(R1 + (c & 1) * ABUF, SAa, Bs + (c & 1) * BBUF,
                               mb, nb, g, tg, acc);
        __syncthreads();
    }

    // overlap: stage first We2 chunk now (buf 0; last GEMM1 B used buf 1)
    stageB(bs_u32, 0, gWe2r, 0, tid); CP_COMMIT();

    // ---- epi1: mid = tf32(silu(acc + radial*w256 + be1)) -> act (aliases A bufs) ----
    #pragma unroll
    for (int mt = 0; mt < 2; mt++) {
        int r0 = mb + mt * 16 + g;
        float rl = s_rad[r0], rh = s_rad[r0 + 8];
        #pragma unroll
        for (int nt = 0; nt < 8; nt++) {
            int cl = nb + nt * 8 + 2 * tg;
            act[r0 * SB + cl]           = __uint_as_float(tf32r(silu_f(acc[mt][nt][0] + rl * s_w256[cl]     + s_b1[cl])));
            act[r0 * SB + cl + 1]       = __uint_as_float(tf32r(silu_f(acc[mt][nt][1] + rl * s_w256[cl + 1] + s_b1[cl + 1])));
            act[(r0 + 8) * SB + cl]     = __uint_as_float(tf32r(silu_f(acc[mt][nt][2] + rh * s_w256[cl]     + s_b1[cl])));
            act[(r0 + 8) * SB + cl + 1] = __uint_as_float(tf32r(silu_f(acc[mt][nt][3] + rh * s_w256[cl + 1] + s_b1[cl + 1])));
            acc[mt][nt][0] = 0.f; acc[mt][nt][1] = 0.f; acc[mt][nt][2] = 0.f; acc[mt][nt][3] = 0.f;
        }
    }
    __syncthreads();

    // ======== GEMM2: mid @ We2, K=128, 4 chunks (A = act) ========
    #pragma unroll 1
    for (int c = 0; c < 4; c++) {
        if (c < 3) {
            stageB(bs_u32, (c + 1) & 1, gWe2r, (c + 1) * 32, tid);
            CP_COMMIT(); cp_wait<1>();
        } else cp_wait<0>();
        __syncthreads();
        warp_gemm_chunk<false>(act + c * 32, SB, Bs + (c & 1) * BBUF, mb, nb, g, tg, acc);
        __syncthreads();
    }

    stageB(bs_u32, 0, gWc1r, 0, tid); CP_COMMIT();

    // ---- epi2: ef_uns = silu(acc + be2) -> act ----
    #pragma unroll
    for (int mt = 0; mt < 2; mt++) {
        int r0 = mb + mt * 16 + g;
        #pragma unroll
        for (int nt = 0; nt < 8; nt++) {
            int cl = nb + nt * 8 + 2 * tg;
            act[r0 * SB + cl]           = silu_f(acc[mt][nt][0] + s_b2[cl]);
            act[r0 * SB + cl + 1]       = silu_f(acc[mt][nt][1] + s_b2[cl + 1]);
            act[(r0 + 8) * SB + cl]     = silu_f(acc[mt][nt][2] + s_b2[cl]);
            act[(r0 + 8) * SB + cl + 1] = silu_f(acc[mt][nt][3] + s_b2[cl + 1]);
            acc[mt][nt][0] = 0.f; acc[mt][nt][1] = 0.f; acc[mt][nt][2] = 0.f; acc[mt][nt][3] = 0.f;
        }
    }
    __syncthreads();

    // ---- attention: per-row dot, 2 threads per row ----
    {
        int m = tid >> 1, hf = tid & 1;
        float p = 0.f;
        #pragma unroll
        for (int i = 0; i < 16; i++) {
            int cl = hf * 64 + i * 4;
            float4 v = *(float4*)&act[m * SB + cl];
            p += v.x * s_watt[cl] + v.y * s_watt[cl + 1] + v.z * s_watt[cl + 2] + v.w * s_watt[cl + 3];
        }
        p += __shfl_xor_sync(0xffffffffu, p, 1);
        if (!hf) s_att[m] = 1.f / (1.f + __expf(-(p + s_x[0])));
    }
    __syncthreads();

    // ---- scale ef by att, write ef_out, scatter g_agg ----
    {
        int m = tid >> 1, hf = tid & 1;
        float a = s_att[m];
        long long e = e0 + m;
        bool ok = (e < E);
        int rnode = s_row[m];
        #pragma unroll
        for (int i = 0; i < 16; i++) {
            int cl = hf * 64 + i * 4;
            float4 v = *(float4*)&act[m * SB + cl];
            v.x *= a; v.y *= a; v.z *= a; v.w *= a;
            *(float4*)&act[m * SB + cl] = v;
            if (ok) {
                *(float4*)&ef_out[(size_t)e * 128 + cl] = v;
                red4(&g_agg[(size_t)rnode * 128 + cl], v.x, v.y, v.z, v.w);
            }
        }
    }
    __syncthreads();

    // ======== GEMM3: ef @ Wc1, K=128 (A = act, cvt at load) ========
    #pragma unroll 1
    for (int c = 0; c < 4; c++) {
        if (c < 3) {
            stageB(bs_u32, (c + 1) & 1, gWc1r, (c + 1) * 32, tid);
            CP_COMMIT(); cp_wait<1>();
        } else cp_wait<0>();
        __syncthreads();
        warp_gemm_chunk<true>(act + c * 32, SB, Bs + (c & 1) * BBUF, mb, nb, g, tg, acc);
        __syncthreads();
    }

    // ---- epi3: cw = silu(acc + bc1) . Wc2, in-register partial dots ----
    {
        float cw0[2] = {0.f, 0.f}, cw1[2] = {0.f, 0.f};
        #pragma unroll
        for (int mt = 0; mt < 2; mt++) {
            #pragma unroll
            for (int nt = 0; nt < 8; nt++) {
                int cl = nb + nt * 8 + 2 * tg;
                cw0[mt] += silu_f(acc[mt][nt][0] + s_bc1[cl])     * s_wc2[cl];
                cw0[mt] += silu_f(acc[mt][nt][1] + s_bc1[cl + 1]) * s_wc2[cl + 1];
                cw1[mt] += silu_f(acc[mt][nt][2] + s_bc1[cl])     * s_wc2[cl];
                cw1[mt] += silu_f(acc[mt][nt][3] + s_bc1[cl + 1]) * s_wc2[cl + 1];
            }
        }
        #pragma unroll
        for (int mt = 0; mt < 2; mt++) {
            cw0[mt] += __shfl_xor_sync(0xffffffffu, cw0[mt], 1);
            cw0[mt] += __shfl_xor_sync(0xffffffffu, cw0[mt], 2);
            cw1[mt] += __shfl_xor_sync(0xffffffffu, cw1[mt], 1);
            cw1[mt] += __shfl_xor_sync(0xffffffffu, cw1[mt], 2);
            if (tg == 0) {
                float* dst = half ? s_cwB : s_cwA;
                int r0 = mb + mt * 16 + g;
                dst[r0] = cw0[mt];
                dst[r0 + 8] = cw1[mt];
            }
        }
    }
    __syncthreads();

    // ---- clipped trans scatter ----
    if (tid < 128) {
        long long e = e0 + tid;
        if (e < E) {
            float cw = s_cwA[tid] + s_cwB[tid];
            int r = s_row[tid];
            float t0 = fminf(10.f, fmaxf(-10.f, s_cd[tid * 3 + 0] * cw));
            float t1 = fminf(10.f, fmaxf(-10.f, s_cd[tid * 3 + 1] * cw));
            float t2 = fminf(10.f, fmaxf(-10.f, s_cd[tid * 3 + 2] * cw));
            red4(&g_aggc[r * 4], t0, t1, t2, 1.0f);
        }
    }
}

// ================= node kernel =================
__global__ __launch_bounds__(256, 2) void node_kernel(
    const float* __restrict__ h, const float* __restrict__ coord,
    const float* __restrict__ bn1, const float* __restrict__ bn2,
    float* __restrict__ h_out, float* __restrict__ coord_out, int Nn)
{
    extern __shared__ float sm[];
    float* R1  = sm + F_R1;
    float* act = sm + F_R1;
    float* Bs  = sm + F_BS;
    float* M   = sm + F_MISC;
    float* s_b1 = M + 896;
    float* s_b2 = M + 1024;

    const u32 r1_u32 = smem_u32(R1);
    const u32 bs_u32 = smem_u32(Bs);
    const int tid = threadIdx.x;
    const int wid = tid >> 5, lane = tid & 31;
    const int g = lane >> 2, tg = lane & 3;
    const int mb = (wid >> 1) * 32, nb = (wid & 1) * 64;
    const int n0 = blockIdx.x * 128;

    if (tid < 128) { s_b1[tid] = bn1[tid]; s_b2[tid] = bn2[tid]; }
    __syncthreads();

    auto stageA = [&](int c, int buf) {
        const float* base = (c < 4) ? (g_h32 + (size_t)(c * 32))
                                    : (g_agg + (size_t)((c - 4) * 32));
        #pragma unroll
        for (int i = tid; i < 1024; i += 256) {
            int m = i >> 3, q = i & 7;
            int n = n0 + m; if (n >= Nn) n = 0;
            cpa16(r1_u32 + ((u32)buf * ABUF + (u32)(m * SAa + q * 4)) * 4,
                  base + (size_t)n * 128 + q * 4);
        }
    };

    float acc[2][8][4];
    #pragma unroll
    for (int mt = 0; mt < 2; mt++)
        #pragma unroll
        for (int nt = 0; nt < 8; nt++)
            #pragma unroll
            for (int t = 0; t < 4; t++) acc[mt][nt][t] = 0.f;

    // GEMM1: [h|agg] @ Wn1, K=256, 8 chunks
    stageA(0, 0); stageB(bs_u32, 0, gWn1r, 0, tid); CP_COMMIT();
    #pragma unroll 1
    for (int c = 0; c < 8; c++) {
        if (c < 7) {
            stageA(c + 1, (c + 1) & 1);
            stageB(bs_u32, (c + 1) & 1, gWn1r, (c + 1) * 32, tid);
            CP_COMMIT(); cp_wait<1>();
        } else cp_wait<0>();
        __syncthreads();
        warp_gemm_chunk<true>(R1 + (c & 1) * ABUF, SAa, Bs + (c & 1) * BBUF,
                              mb, nb, g, tg, acc);
        __syncthreads();
    }

    stageB(bs_u32, 0, gWn2r, 0, tid); CP_COMMIT();

    // epi1: mid = tf32(silu(acc + bn1)) -> act
    #pragma unroll
    for (int mt = 0; mt < 2; mt++) {
        int r0 = mb + mt * 16 + g;
        #pragma unroll
        for (int nt = 0; nt < 8; nt++) {
            int cl = nb + nt * 8 + 2 * tg;
            act[r0 * SB + cl]           = __uint_as_float(tf32r(silu_f(acc[mt][nt][0] + s_b1[cl])));
            act[r0 * SB + cl + 1]       = __uint_as_float(tf32r(silu_f(acc[mt][nt][1] + s_b1[cl + 1])));
            act[(r0 + 8) * SB + cl]     = __uint_as_float(tf32r(silu_f(acc[mt][nt][2] + s_b1[cl])));
            act[(r0 + 8) * SB + cl + 1] = __uint_as_float(tf32r(silu_f(acc[mt][nt][3] + s_b1[cl + 1])));
            acc[mt][nt][0] = 0.f; acc[mt][nt][1] = 0.f; acc[mt][nt][2] = 0.f; acc[mt][nt][3] = 0.f;
        }
    }
    __syncthreads();

    // GEMM2: mid @ Wn2, K=128, 4 chunks
    #pragma unroll 1
    for (int c = 0; c < 4; c++) {
        if (c < 3) {
            stageB(bs_u32, (c + 1) & 1, gWn2r, (c + 1) * 32, tid);
            CP_COMMIT(); cp_wait<1>();
        } else cp_wait<0>();
        __syncthreads();
        warp_gemm_chunk<false>(act + c * 32, SB, Bs + (c & 1) * BBUF, mb, nb, g, tg, acc);
        __syncthreads();
    }

    // epi2: write acc + bn2 to act
    #pragma unroll
    for (int mt = 0; mt < 2; mt++) {
        int r0 = mb + mt * 16 + g;
        #pragma unroll
        for (int nt = 0; nt < 8; nt++) {
            int cl = nb + nt * 8 + 2 * tg;
            act[r0 * SB + cl]           = acc[mt][nt][0] + s_b2[cl];
            act[r0 * SB + cl + 1]       = acc[mt][nt][1] + s_b2[cl + 1];
            act[(r0 + 8) * SB + cl]     = acc[mt][nt][2] + s_b2[cl];
            act[(r0 + 8) * SB + cl + 1] = acc[mt][nt][3] + s_b2[cl + 1];
        }
    }
    __syncthreads();

    // residual + store h_out
    {
        int m = tid >> 1, hf = tid & 1;
        int n = n0 + m;
        if (n < Nn) {
            #pragma unroll
            for (int i = 0; i < 16; i++) {
                int cl = hf * 64 + i * 4;
                float4 v = *(float4*)&act[m * SB + cl];
                float4 hh = *(const float4*)&h[(size_t)n * 128 + cl];
                v.x += hh.x; v.y += hh.y; v.z += hh.z; v.w += hh.w;
                *(float4*)&h_out[(size_t)n * 128 + cl] = v;
            }
        }
    }

    // coord update
    if (tid < 128) {
        int n = n0 + tid;
        if (n < Nn) {
            float cnt = fmaxf(g_aggc[n * 4 + 3], 1.f);
            #pragma unroll
            for (int d = 0; d < 3; d++) {
                float m = g_aggc[n * 4 + d] / cnt;
                m = fminf(10.f, fmaxf(-10.f, m));
                coord_out[n * 3 + d] = coord[n * 3 + d] + m;
            }
        }
    }
}

// ---------------- launch ----------------
extern "C" void kernel_launch(void* const* d_in, const int* in_sizes, int n_in,
                              void* d_out, int out_size)
{
    const float* h     = (const float*)d_in[0];
    const void*  ei    = d_in[1];
    const float* coord = (const float*)d_in[2];
    const float* We1 = (const float*)d_in[3];  const float* be1 = (const float*)d_in[4];
    const float* We2 = (const float*)d_in[5];  const float* be2 = (const float*)d_in[6];
    const float* Watt= (const float*)d_in[7];  const float* batt= (const float*)d_in[8];
    const float* Wc1 = (const float*)d_in[9];  const float* bc1 = (const float*)d_in[10];
    const float* Wc2 = (const float*)d_in[11];
    const float* Wn1 = (const float*)d_in[12]; const float* bn1 = (const float*)d_in[13];
    const float* Wn2 = (const float*)d_in[14]; const float* bn2 = (const float*)d_in[15];

    int Nn = in_sizes[0] / Dq;
    int E  = in_sizes[1] / 2;

    float* out       = (float*)d_out;
    float* h_out     = out;
    float* coord_out = out + (size_t)Nn * Dq;
    float* ef_out    = coord_out + (size_t)Nn * 3;

    static int smem_set = 0;
    if (!smem_set) {
        cudaFuncSetAttribute(edge_kernel, cudaFuncAttributeMaxDynamicSharedMemorySize, SMEM_BYTES);
        cudaFuncSetAttribute(node_kernel, cudaFuncAttributeMaxDynamicSharedMemorySize, SMEM_BYTES);
        smem_set = 1;
    }

    float *dh32, *dWe1r, *dWe2r, *dWc1r, *dWn1r, *dWn2r;
    cudaGetSymbolAddress((void**)&dh32,  g_h32);
    cudaGetSymbolAddress((void**)&dWe1r, gWe1r);
    cudaGetSymbolAddress((void**)&dWe2r, gWe2r);
    cudaGetSymbolAddress((void**)&dWc1r, gWc1r);
    cudaGetSymbolAddress((void**)&dWn1r, gWn1r);
    cudaGetSymbolAddress((void**)&dWn2r, gWn2r);

    detect_kernel<<<1, 32>>>((const int*)ei);
    zero_kernel<<<1024, 256>>>(Nn);
    prep_cvt<<<2048, 256>>>(h,   dh32,  Nn * 128);
    prep_cvt<<<128, 256>>>(We1, dWe1r, 256 * 128);
    prep_cvt<<<64, 256>>>(We2, dWe2r, 128 * 128);
    prep_cvt<<<64, 256>>>(Wc1, dWc1r, 128 * 128);
    prep_cvt<<<128, 256>>>(Wn1, dWn1r, 256 * 128);
    prep_cvt<<<64, 256>>>(Wn2, dWn2r, 128 * 128);

    edge_kernel<<<(E + 127) / 128, 256, SMEM_BYTES>>>(
        ei, coord, We1, be1, be2, Watt, batt, bc1, Wc2, ef_out, E);

    node_kernel<<<(Nn + 127) / 128, 256, SMEM_BYTES>>>(
        h, coord, bn1, bn2, h_out, coord_out, Nn);
}

// round 9
// speedup vs baseline: 1.4920x; 1.4920x over previous
#include <cuda_runtime.h>
#include <cstdint>

typedef uint32_t u32;

#define Dq 128
#define MAXN 50000

// ---------------- device scratch ----------------
__device__ float g_agg[(size_t)MAXN * Dq];
__device__ float g_aggc[(size_t)MAXN * 4];
__device__ int   g_is64;
__device__ float gWe1r[256 * 128];           // tf32-rounded weights (k-major)
__device__ float gWe2r[128 * 128];
__device__ float gWc1r[128 * 128];
__device__ float gWn1r[256 * 128];
__device__ float gWn2r[128 * 128];

// ---------------- helpers ----------------
__device__ __forceinline__ float silu_f(float x) {
    return x * (1.0f / (1.0f + __expf(-x)));
}
__device__ __forceinline__ u32 tf32r(float f) {
    u32 u; asm("cvt.rna.tf32.f32 %0, %1;" : "=r"(u) : "f"(f)); return u;
}
__device__ __forceinline__ u32 smem_u32(const void* p) {
    u32 a;
    asm("{ .reg .u64 t; cvta.to.shared.u64 t, %1; cvt.u32.u64 %0, t; }" : "=r"(a) : "l"(p));
    return a;
}
__device__ __forceinline__ void cpa16(u32 d, const void* s) {
    asm volatile("cp.async.ca.shared.global [%0], [%1], 16;" :: "r"(d), "l"(s) : "memory");
}
#define CP_COMMIT() asm volatile("cp.async.commit_group;" ::: "memory")
template<int N> __device__ __forceinline__ void cp_wait() {
    asm volatile("cp.async.wait_group %0;" :: "n"(N) : "memory");
}
__device__ __forceinline__ void mma8(float (&d)[4], const u32 (&a)[4], const u32 (&b)[2]) {
    asm volatile("mma.sync.aligned.m16n8k8.row.col.f32.tf32.tf32.f32 "
                 "{%0,%1,%2,%3}, {%4,%5,%6,%7}, {%8,%9}, {%0,%1,%2,%3};"
                 : "+f"(d[0]), "+f"(d[1]), "+f"(d[2]), "+f"(d[3])
                 : "r"(a[0]), "r"(a[1]), "r"(a[2]), "r"(a[3]), "r"(b[0]), "r"(b[1]));
}
__device__ __forceinline__ void red4(float* p, float a, float b, float c, float d) {
    asm volatile("red.global.add.v4.f32 [%0], {%1,%2,%3,%4};"
                 :: "l"(p), "f"(a), "f"(b), "f"(c), "f"(d) : "memory");
}

// ---------------- core warp GEMM: one K=64 chunk (8 k8-steps) ----------------
#define SB 136                // B-chunk / act row stride (128+8)
template<bool CVTA>
__device__ __forceinline__ void warp_gemm_chunk(
    const float* __restrict__ As_, int sa,
    const float* __restrict__ Bs_,
    int mb, int nb, int g, int tg,
    float (*acc)[8][4])
{
    #pragma unroll
    for (int ks = 0; ks < 8; ks++) {
        const int k = ks * 8;
        u32 a[2][4], b[8][2];
        #pragma unroll
        for (int mt = 0; mt < 2; mt++) {
            const float* ap = As_ + (mb + mt * 16 + g) * sa + k + tg;
            float f0 = ap[0], f1 = ap[8 * sa], f2 = ap[4], f3 = ap[8 * sa + 4];
            if (CVTA) {
                a[mt][0] = tf32r(f0); a[mt][1] = tf32r(f1);
                a[mt][2] = tf32r(f2); a[mt][3] = tf32r(f3);
            } else {
                a[mt][0] = __float_as_uint(f0); a[mt][1] = __float_as_uint(f1);
                a[mt][2] = __float_as_uint(f2); a[mt][3] = __float_as_uint(f3);
            }
        }
        #pragma unroll
        for (int nt = 0; nt < 8; nt++) {
            const float* bp = Bs_ + (k + tg) * SB + nb + nt * 8 + g;
            b[nt][0] = __float_as_uint(bp[0]);
            b[nt][1] = __float_as_uint(bp[4 * SB]);
        }
        #pragma unroll
        for (int mt = 0; mt < 2; mt++)
            #pragma unroll
            for (int nt = 0; nt < 8; nt++)
                mma8(acc[mt][nt], a[mt], b[nt]);
    }
}

// ---------------- small kernels ----------------
__global__ void detect_kernel(const int* __restrict__ ei32) {
    if (threadIdx.x == 0 && blockIdx.x == 0) {
        int acc = 0;
        #pragma unroll
        for (int k = 0; k < 128; k++) acc |= ei32[2 * k + 1];
        g_is64 = (acc == 0) ? 1 : 0;
    }
}
__global__ void zero_kernel(int Nn) {
    int stride = gridDim.x * blockDim.x;
    for (int i = blockIdx.x * blockDim.x + threadIdx.x; i < Nn * Dq; i += stride)
        g_agg[i] = 0.f;
    for (int i = blockIdx.x * blockDim.x + threadIdx.x; i < Nn * 4; i += stride)
        g_aggc[i] = 0.f;
}
__global__ void prep_cvt(const float* __restrict__ src, float* __restrict__ dst, int n) {
    int stride = gridDim.x * blockDim.x;
    for (int i = blockIdx.x * blockDim.x + threadIdx.x; i < n; i += stride)
        dst[i] = __uint_as_float(tf32r(src[i]));
}

// ================= edge kernel: 256 edges/block, 512 threads =================
// smem (float offsets):
//  R1 [0, 34816): A-staging 2 x (256 x 68) during each GEMM's A use; act[256][136] aliased
//  Bs [34816, 52224): 2 x 64 x 136
//  M  [52224, 55360): misc
#define E_SA 68
#define E_ABUF (256 * E_SA)      // 17408
#define E_BBUF (64 * SB)         // 8704
#define E_F_BS 34816
#define E_F_MISC 52224
#define E_SMEM_BYTES ((E_F_MISC + 3136) * 4)   // 221440

__global__ __launch_bounds__(512, 1) void edge_kernel(
    const void* __restrict__ ei, const float* __restrict__ coord,
    const float* __restrict__ h, const float* __restrict__ We1,
    const float* __restrict__ be1, const float* __restrict__ be2,
    const float* __restrict__ Watt, const float* __restrict__ batt,
    const float* __restrict__ bc1, const float* __restrict__ Wc2,
    float* __restrict__ ef_out, int E)
{
    extern __shared__ float sm[];
    float* R1  = sm;
    float* act = sm;
    float* Bs  = sm + E_F_BS;
    float* M   = sm + E_F_MISC;
    int*   s_row = (int*)(M);
    int*   s_col = (int*)(M + 256);
    float* s_cd  = M + 512;    // 768
    float* s_rad = M + 1280;   // 256
    float* s_w256= M + 1536;
    float* s_b1  = M + 1664;
    float* s_b2  = M + 1792;
    float* s_bc1 = M + 1920;
    float* s_watt= M + 2048;
    float* s_wc2 = M + 2176;
    float* s_att = M + 2304;   // 256
    float* s_cwA = M + 2560;   // 256
    float* s_cwB = M + 2816;   // 256
    float* s_x   = M + 3072;

    const u32 r1_u32 = smem_u32(R1);
    const u32 bs_u32 = smem_u32(Bs);
    const int tid = threadIdx.x;
    const int wid = tid >> 5, lane = tid & 31;
    const int g = lane >> 2, tg = lane & 3;
    const int mb = (wid >> 1) * 32, nb = (wid & 1) * 64;
    const int half = wid & 1;
    const long long e0 = (long long)blockIdx.x * 256;

    // ---- meta + small vectors ----
    if (tid < 256) {
        long long e = e0 + tid;
        int r = 0, c = 0;
        if (e < E) {
            if (g_is64) {
                const long long* p = (const long long*)ei;
                r = (int)p[e]; c = (int)p[E + e];
            } else {
                const int* p = (const int*)ei;
                r = p[e]; c = p[E + e];
            }
        }
        s_row[tid] = r; s_col[tid] = c;
        float dx = coord[r * 3 + 0] - coord[c * 3 + 0];
        float dy = coord[r * 3 + 1] - coord[c * 3 + 1];
        float dz = coord[r * 3 + 2] - coord[c * 3 + 2];
        s_cd[tid * 3 + 0] = dx; s_cd[tid * 3 + 1] = dy; s_cd[tid * 3 + 2] = dz;
        s_rad[tid] = dx * dx + dy * dy + dz * dz;
        if (tid < 128) {
            s_w256[tid] = We1[256 * 128 + tid];
            s_b1[tid] = be1[tid]; s_b2[tid] = be2[tid]; s_bc1[tid] = bc1[tid];
            s_watt[tid] = Watt[tid]; s_wc2[tid] = Wc2[tid];
            if (tid == 0) s_x[0] = batt[0];
        }
    }
    __syncthreads();

    // A-chunk stage: chunk c (0..3): rows h[row] (c<2) or h[col], cols (c&1)*64
    auto stageA = [&](int c, int buf) {
        const float* base = h + (size_t)((c & 1) * 64);
        #pragma unroll
        for (int i = tid; i < 4096; i += 512) {
            int m = i >> 4, q = i & 15;
            int node = (c >= 2) ? s_col[m] : s_row[m];
            cpa16(r1_u32 + ((u32)buf * E_ABUF + (u32)(m * E_SA + q * 4)) * 4,
                  base + (size_t)node * 128 + q * 4);
        }
    };
    // stage a [64][128] weight chunk
    auto stageB = [&](int buf, const float* W, int k0) {
        #pragma unroll
        for (int i = tid; i < 2048; i += 512) {
            int k = i >> 5, q = i & 31;
            cpa16(bs_u32 + (u32)(buf * E_BBUF + k * SB + q * 4) * 4,
                  W + (size_t)(k0 + k) * 128 + q * 4);
        }
    };

    float acc[2][8][4];
    #pragma unroll
    for (int mt = 0; mt < 2; mt++)
        #pragma unroll
        for (int nt = 0; nt < 8; nt++)
            #pragma unroll
            for (int t = 0; t < 4; t++) acc[mt][nt][t] = 0.f;

    // ======== GEMM1: K=256 over [h_row|h_col], 4 chunks of K=64 ========
    stageA(0, 0); stageB(0, gWe1r, 0); CP_COMMIT();
    #pragma unroll 1
    for (int c = 0; c < 4; c++) {
        if (c < 3) {
            stageA(c + 1, (c + 1) & 1);
            stageB((c + 1) & 1, gWe1r, (c + 1) * 64);
            CP_COMMIT(); cp_wait<1>();
        } else cp_wait<0>();
        __syncthreads();
        warp_gemm_chunk<true>(R1 + (c & 1) * E_ABUF, E_SA, Bs + (c & 1) * E_BBUF,
                              mb, nb, g, tg, acc);
        __syncthreads();
    }

    // prefetch first We2 chunk during epilogue (buf 0; last GEMM1 B was buf 1)
    stageB(0, gWe2r, 0); CP_COMMIT();

    // ---- epi1: mid = tf32(silu(acc + radial*w256 + be1)) -> act (aliases A bufs) ----
    #pragma unroll
    for (int mt = 0; mt < 2; mt++) {
        int r0 = mb + mt * 16 + g;
        float rl = s_rad[r0], rh = s_rad[r0 + 8];
        #pragma unroll
        for (int nt = 0; nt < 8; nt++) {
            int cl = nb + nt * 8 + 2 * tg;
            act[r0 * SB + cl]           = __uint_as_float(tf32r(silu_f(acc[mt][nt][0] + rl * s_w256[cl]     + s_b1[cl])));
            act[r0 * SB + cl + 1]       = __uint_as_float(tf32r(silu_f(acc[mt][nt][1] + rl * s_w256[cl + 1] + s_b1[cl + 1])));
            act[(r0 + 8) * SB + cl]     = __uint_as_float(tf32r(silu_f(acc[mt][nt][2] + rh * s_w256[cl]     + s_b1[cl])));
            act[(r0 + 8) * SB + cl + 1] = __uint_as_float(tf32r(silu_f(acc[mt][nt][3] + rh * s_w256[cl + 1] + s_b1[cl + 1])));
            acc[mt][nt][0] = 0.f; acc[mt][nt][1] = 0.f; acc[mt][nt][2] = 0.f; acc[mt][nt][3] = 0.f;
        }
    }
    __syncthreads();

    // ======== GEMM2: mid @ We2, K=128, 2 chunks (A = act) ========
    #pragma unroll 1
    for (int c = 0; c < 2; c++) {
        if (c == 0) { stageB(1, gWe2r, 64); CP_COMMIT(); cp_wait<1>(); }
        else cp_wait<0>();
        __syncthreads();
        warp_gemm_chunk<false>(act + c * 64, SB, Bs + (c & 1) * E_BBUF, mb, nb, g, tg, acc);
        __syncthreads();
    }

    stageB(0, gWc1r, 0); CP_COMMIT();

    // ---- epi2: ef_uns = silu(acc + be2) -> act ----
    #pragma unroll
    for (int mt = 0; mt < 2; mt++) {
        int r0 = mb + mt * 16 + g;
        #pragma unroll
        for (int nt = 0; nt < 8; nt++) {
            int cl = nb + nt * 8 + 2 * tg;
            act[r0 * SB + cl]           = silu_f(acc[mt][nt][0] + s_b2[cl]);
            act[r0 * SB + cl + 1]       = silu_f(acc[mt][nt][1] + s_b2[cl + 1]);
            act[(r0 + 8) * SB + cl]     = silu_f(acc[mt][nt][2] + s_b2[cl]);
            act[(r0 + 8) * SB + cl + 1] = silu_f(acc[mt][nt][3] + s_b2[cl + 1]);
            acc[mt][nt][0] = 0.f; acc[mt][nt][1] = 0.f; acc[mt][nt][2] = 0.f; acc[mt][nt][3] = 0.f;
        }
    }
    __syncthreads();

    // ---- attention: per-row dot, 2 threads per row ----
    {
        int m = tid >> 1, hf = tid & 1;
        float p = 0.f;
        #pragma unroll
        for (int i = 0; i < 16; i++) {
            int cl = hf * 64 + i * 4;
            float4 v = *(float4*)&act[m * SB + cl];
            p += v.x * s_watt[cl] + v.y * s_watt[cl + 1] + v.z * s_watt[cl + 2] + v.w * s_watt[cl + 3];
        }
        p += __shfl_xor_sync(0xffffffffu, p, 1);
        if (!hf) s_att[m] = 1.f / (1.f + __expf(-(p + s_x[0])));
    }
    __syncthreads();

    // ---- scale ef by att, write ef_out, scatter g_agg ----
    {
        int m = tid >> 1, hf = tid & 1;
        float a = s_att[m];
        long long e = e0 + m;
        bool ok = (e < E);
        int rnode = s_row[m];
        #pragma unroll
        for (int i = 0; i < 16; i++) {
            int cl = hf * 64 + i * 4;
            float4 v = *(float4*)&act[m * SB + cl];
            v.x *= a; v.y *= a; v.z *= a; v.w *= a;
            *(float4*)&act[m * SB + cl] = v;
            if (ok) {
                *(float4*)&ef_out[(size_t)e * 128 + cl] = v;
                red4(&g_agg[(size_t)rnode * 128 + cl], v.x, v.y, v.z, v.w);
            }
        }
    }
    __syncthreads();

    // ======== GEMM3: ef @ Wc1, K=128 (A = act, cvt at load) ========
    #pragma unroll 1
    for (int c = 0; c < 2; c++) {
        if (c == 0) { stageB(1, gWc1r, 64); CP_COMMIT(); cp_wait<1>(); }
        else cp_wait<0>();
        __syncthreads();
        warp_gemm_chunk<true>(act + c * 64, SB, Bs + (c & 1) * E_BBUF, mb, nb, g, tg, acc);
        __syncthreads();
    }

    // ---- epi3: cw = silu(acc + bc1) . Wc2, in-register partial dots ----
    {
        float cw0[2] = {0.f, 0.f}, cw1[2] = {0.f, 0.f};
        #pragma unroll
        for (int mt = 0; mt < 2; mt++) {
            #pragma unroll
            for (int nt = 0; nt < 8; nt++) {
                int cl = nb + nt * 8 + 2 * tg;
                cw0[mt] += silu_f(acc[mt][nt][0] + s_bc1[cl])     * s_wc2[cl];
                cw0[mt] += silu_f(acc[mt][nt][1] + s_bc1[cl + 1]) * s_wc2[cl + 1];
                cw1[mt] += silu_f(acc[mt][nt][2] + s_bc1[cl])     * s_wc2[cl];
                cw1[mt] += silu_f(acc[mt][nt][3] + s_bc1[cl + 1]) * s_wc2[cl + 1];
            }
        }
        #pragma unroll
        for (int mt = 0; mt < 2; mt++) {
            cw0[mt] += __shfl_xor_sync(0xffffffffu, cw0[mt], 1);
            cw0[mt] += __shfl_xor_sync(0xffffffffu, cw0[mt], 2);
            cw1[mt] += __shfl_xor_sync(0xffffffffu, cw1[mt], 1);
            cw1[mt] += __shfl_xor_sync(0xffffffffu, cw1[mt], 2);
            if (tg == 0) {
                float* dst = half ? s_cwB : s_cwA;
                int r0 = mb + mt * 16 + g;
                dst[r0] = cw0[mt];
                dst[r0 + 8] = cw1[mt];
            }
        }
    }
    __syncthreads();

    // ---- clipped trans scatter ----
    if (tid < 256) {
        long long e = e0 + tid;
        if (e < E) {
            float cw = s_cwA[tid] + s_cwB[tid];
            int r = s_row[tid];
            float t0 = fminf(10.f, fmaxf(-10.f, s_cd[tid * 3 + 0] * cw));
            float t1 = fminf(10.f, fmaxf(-10.f, s_cd[tid * 3 + 1] * cw));
            float t2 = fminf(10.f, fmaxf(-10.f, s_cd[tid * 3 + 2] * cw));
            red4(&g_aggc[r * 4], t0, t1, t2, 1.0f);
        }
    }
}

// ================= node kernel: 128 nodes/block, 256 threads =================
// smem: R1 [0, 17408): A-staging 2 x (128 x 68) / act[128][136] aliased
//       Bs [17408, 34816), M [34816, 35328)
#define N_ABUF (128 * E_SA)     // 8704
#define N_F_BS 17408
#define N_F_MISC 34816
#define N_SMEM_BYTES ((N_F_MISC + 512) * 4)   // 141312

__global__ __launch_bounds__(256, 1) void node_kernel(
    const float* __restrict__ h, const float* __restrict__ coord,
    const float* __restrict__ bn1, const float* __restrict__ bn2,
    float* __restrict__ h_out, float* __restrict__ coord_out, int Nn)
{
    extern __shared__ float sm[];
    float* R1  = sm;
    float* act = sm;
    float* Bs  = sm + N_F_BS;
    float* M   = sm + N_F_MISC;
    float* s_b1 = M;
    float* s_b2 = M + 128;

    const u32 r1_u32 = smem_u32(R1);
    const u32 bs_u32 = smem_u32(Bs);
    const int tid = threadIdx.x;
    const int wid = tid >> 5, lane = tid & 31;
    const int g = lane >> 2, tg = lane & 3;
    const int mb = (wid >> 1) * 32, nb = (wid & 1) * 64;
    const int n0 = blockIdx.x * 128;

    if (tid < 128) { s_b1[tid] = bn1[tid]; s_b2[tid] = bn2[tid]; }
    __syncthreads();

    auto stageA = [&](int c, int buf) {
        const float* base = (c < 2) ? (h + (size_t)(c * 64))
                                    : (g_agg + (size_t)((c - 2) * 64));
        #pragma unroll
        for (int i = tid; i < 2048; i += 256) {
            int m = i >> 4, q = i & 15;
            int n = n0 + m; if (n >= Nn) n = 0;
            cpa16(r1_u32 + ((u32)buf * N_ABUF + (u32)(m * E_SA + q * 4)) * 4,
                  base + (size_t)n * 128 + q * 4);
        }
    };
    auto stageB = [&](int buf, const float* W, int k0) {
        #pragma unroll
        for (int i = tid; i < 2048; i += 256) {
            int k = i >> 5, q = i & 31;
            cpa16(bs_u32 + (u32)(buf * E_BBUF + k * SB + q * 4) * 4,
                  W + (size_t)(k0 + k) * 128 + q * 4);
        }
    };

    float acc[2][8][4];
    #pragma unroll
    for (int mt = 0; mt < 2; mt++)
        #pragma unroll
        for (int nt = 0; nt < 8; nt++)
            #pragma unroll
            for (int t = 0; t < 4; t++) acc[mt][nt][t] = 0.f;

    // GEMM1: [h|agg] @ Wn1, K=256, 4 chunks of K=64
    stageA(0, 0); stageB(0, gWn1r, 0); CP_COMMIT();
    #pragma unroll 1
    for (int c = 0; c < 4; c++) {
        if (c < 3) {
            stageA(c + 1, (c + 1) & 1);
            stageB((c + 1) & 1, gWn1r, (c + 1) * 64);
            CP_COMMIT(); cp_wait<1>();
        } else cp_wait<0>();
        __syncthreads();
        warp_gemm_chunk<true>(R1 + (c & 1) * N_ABUF, E_SA, Bs + (c & 1) * E_BBUF,
                              mb, nb, g, tg, acc);
        __syncthreads();
    }

    stageB(0, gWn2r, 0); CP_COMMIT();

    // epi1: mid = tf32(silu(acc + bn1)) -> act
    #pragma unroll
    for (int mt = 0; mt < 2; mt++) {
        int r0 = mb + mt * 16 + g;
        #pragma unroll
        for (int nt = 0; nt < 8; nt++) {
            int cl = nb + nt * 8 + 2 * tg;
            act[r0 * SB + cl]           = __uint_as_float(tf32r(silu_f(acc[mt][nt][0] + s_b1[cl])));
            act[r0 * SB + cl + 1]       = __uint_as_float(tf32r(silu_f(acc[mt][nt][1] + s_b1[cl + 1])));
            act[(r0 + 8) * SB + cl]     = __uint_as_float(tf32r(silu_f(acc[mt][nt][2] + s_b1[cl])));
            act[(r0 + 8) * SB + cl + 1] = __uint_as_float(tf32r(silu_f(acc[mt][nt][3] + s_b1[cl + 1])));
            acc[mt][nt][0] = 0.f; acc[mt][nt][1] = 0.f; acc[mt][nt][2] = 0.f; acc[mt][nt][3] = 0.f;
        }
    }
    __syncthreads();

    // GEMM2: mid @ Wn2, K=128, 2 chunks
    #pragma unroll 1
    for (int c = 0; c < 2; c++) {
        if (c == 0) { stageB(1, gWn2r, 64); CP_COMMIT(); cp_wait<1>(); }
        else cp_wait<0>();
        __syncthreads();
        warp_gemm_chunk<false>(act + c * 64, SB, Bs + (c & 1) * E_BBUF, mb, nb, g, tg, acc);
        __syncthreads();
    }

    // epi2: write acc + bn2 to act
    #pragma unroll
    for (int mt = 0; mt < 2; mt++) {
        int r0 = mb + mt * 16 + g;
        #pragma unroll
        for (int nt = 0; nt < 8; nt++) {
            int cl = nb + nt * 8 + 2 * tg;
            act[r0 * SB + cl]           = acc[mt][nt][0] + s_b2[cl];
            act[r0 * SB + cl + 1]       = acc[mt][nt][1] + s_b2[cl + 1];
            act[(r0 + 8) * SB + cl]     = acc[mt][nt][2] + s_b2[cl];
            act[(r0 + 8) * SB + cl + 1] = acc[mt][nt][3] + s_b2[cl + 1];
        }
    }
    __syncthreads();

    // residual + store h_out
    {
        int m = tid >> 1, hf = tid & 1;
        int n = n0 + m;
        if (n < Nn) {
            #pragma unroll
            for (int i = 0; i < 16; i++) {
                int cl = hf * 64 + i * 4;
                float4 v = *(float4*)&act[m * SB + cl];
                float4 hh = *(const float4*)&h[(size_t)n * 128 + cl];
                v.x += hh.x; v.y += hh.y; v.z += hh.z; v.w += hh.w;
                *(float4*)&h_out[(size_t)n * 128 + cl] = v;
            }
        }
    }

    // coord update
    if (tid < 128) {
        int n = n0 + tid;
        if (n < Nn) {
            float cnt = fmaxf(g_aggc[n * 4 + 3], 1.f);
            #pragma unroll
            for (int d = 0; d < 3; d++) {
                float m = g_aggc[n * 4 + d] / cnt;
                m = fminf(10.f, fmaxf(-10.f, m));
                coord_out[n * 3 + d] = coord[n * 3 + d] + m;
            }
        }
    }
}

// ---------------- launch ----------------
extern "C" void kernel_launch(void* const* d_in, const int* in_sizes, int n_in,
                              void* d_out, int out_size)
{
    const float* h     = (const float*)d_in[0];
    const void*  ei    = d_in[1];
    const float* coord = (const float*)d_in[2];
    const float* We1 = (const float*)d_in[3];  const float* be1 = (const float*)d_in[4];
    const float* We2 = (const float*)d_in[5];  const float* be2 = (const float*)d_in[6];
    const float* Watt= (const float*)d_in[7];  const float* batt= (const float*)d_in[8];
    const float* Wc1 = (const float*)d_in[9];  const float* bc1 = (const float*)d_in[10];
    const float* Wc2 = (const float*)d_in[11];
    const float* Wn1 = (const float*)d_in[12]; const float* bn1 = (const float*)d_in[13];
    const float* Wn2 = (const float*)d_in[14]; const float* bn2 = (const float*)d_in[15];

    int Nn = in_sizes[0] / Dq;
    int E  = in_sizes[1] / 2;

    float* out       = (float*)d_out;
    float* h_out     = out;
    float* coord_out = out + (size_t)Nn * Dq;
    float* ef_out    = coord_out + (size_t)Nn * 3;

    static int smem_set = 0;
    if (!smem_set) {
        cudaFuncSetAttribute(edge_kernel, cudaFuncAttributeMaxDynamicSharedMemorySize, E_SMEM_BYTES);
        cudaFuncSetAttribute(node_kernel, cudaFuncAttributeMaxDynamicSharedMemorySize, N_SMEM_BYTES);
        smem_set = 1;
    }

    float *dWe1r, *dWe2r, *dWc1r, *dWn1r, *dWn2r;
    cudaGetSymbolAddress((void**)&dWe1r, gWe1r);
    cudaGetSymbolAddress((void**)&dWe2r, gWe2r);
    cudaGetSymbolAddress((void**)&dWc1r, gWc1r);
    cudaGetSymbolAddress((void**)&dWn1r, gWn1r);
    cudaGetSymbolAddress((void**)&dWn2r, gWn2r);

    detect_kernel<<<1, 32>>>((const int*)ei);
    zero_kernel<<<1024, 256>>>(Nn);
    prep_cvt<<<128, 256>>>(We1, dWe1r, 256 * 128);
    prep_cvt<<<64, 256>>>(We2, dWe2r, 128 * 128);
    prep_cvt<<<64, 256>>>(Wc1, dWc1r, 128 * 128);
    prep_cvt<<<128, 256>>>(Wn1, dWn1r, 256 * 128);
    prep_cvt<<<64, 256>>>(Wn2, dWn2r, 128 * 128);

    edge_kernel<<<(E + 255) / 256, 512, E_SMEM_BYTES>>>(
        ei, coord, h, We1, be1, be2, Watt, batt, bc1, Wc2, ef_out, E);

    node_kernel<<<(Nn + 127) / 128, 256, N_SMEM_BYTES>>>(
        h, coord, bn1, bn2, h_out, coord_out, Nn);
}